// round 11
// baseline (speedup 1.0000x reference)
#include <cuda_runtime.h>
#include <cstdint>

// out[b,m] = dot(inputs[b,m,:], W[m,:]) + bias[m]
// B=1024, M=2048, I=128 (32 float4 per row).
//
// PERSISTENT + SOFTWARE-PIPELINED variant:
//   Grid = 148 SMs x 6 blocks, each warp grid-strides over 4-row groups.
//   8 lanes per row, 4 rows per warp-iteration; next iteration's 8 loads are
//   issued BEFORE the current reduction, so the LSU stays fed through the
//   shuffle/store epilogue (~80 cyc) instead of going idle.

static constexpr int M_DIM = 2048;
static constexpr long long TOTAL  = 1024LL * 2048LL;  // B*M outputs
static constexpr long long GROUPS = TOTAL / 4;        // 4-row groups (exact)

struct X8 { float4 a0, a1, a2, a3, b0, b1, b2, b3; };

__device__ __forceinline__ void load8(X8& r, const float4* __restrict__ inp,
                                      const float4* __restrict__ W,
                                      long long grp, int g, int sub)
{
    const long long row = grp * 4 + g;
    const int m = (int)(row & (M_DIM - 1));
    const float4* __restrict__ xr = inp + row * 32 + sub;
    const float4* __restrict__ wr = W   + (long long)m * 32 + sub;
    r.a0 = xr[0];  r.a1 = xr[8];  r.a2 = xr[16];  r.a3 = xr[24];
    r.b0 = wr[0];  r.b1 = wr[8];  r.b2 = wr[16];  r.b3 = wr[24];
}

__device__ __forceinline__ float reduce_dot(const X8& r)
{
    float s0 = r.a0.x * r.b0.x + r.a0.y * r.b0.y + r.a0.z * r.b0.z + r.a0.w * r.b0.w;
    float s1 = r.a1.x * r.b1.x + r.a1.y * r.b1.y + r.a1.z * r.b1.z + r.a1.w * r.b1.w;
    s0 = fmaf(r.a2.x, r.b2.x, s0); s0 = fmaf(r.a2.y, r.b2.y, s0);
    s0 = fmaf(r.a2.z, r.b2.z, s0); s0 = fmaf(r.a2.w, r.b2.w, s0);
    s1 = fmaf(r.a3.x, r.b3.x, s1); s1 = fmaf(r.a3.y, r.b3.y, s1);
    s1 = fmaf(r.a3.z, r.b3.z, s1); s1 = fmaf(r.a3.w, r.b3.w, s1);
    float s = s0 + s1;
    s += __shfl_xor_sync(0xFFFFFFFFu, s, 4);
    s += __shfl_xor_sync(0xFFFFFFFFu, s, 2);
    s += __shfl_xor_sync(0xFFFFFFFFu, s, 1);
    return s;
}

__global__ __launch_bounds__(256, 4)
void rowdot_kernel(const float4* __restrict__ inp,   // [B*M, 32] float4
                   const float4* __restrict__ W,     // [M, 32] float4
                   const float*  __restrict__ bias,  // [M]
                   float* __restrict__ out)          // [B*M]
{
    const int lane = threadIdx.x & 31;
    const int g    = lane >> 3;   // output slot 0..3
    const int sub  = lane & 7;    // position within 8-lane group

    const long long warp   = (long long)blockIdx.x * 8 + (threadIdx.x >> 5);
    const long long stride = (long long)gridDim.x * 8;

    long long grp = warp;
    if (grp >= GROUPS) return;

    X8 cur, nxt;
    load8(cur, inp, W, grp, g, sub);

    for (;;) {
        const long long next_grp = grp + stride;
        const bool have_next = (next_grp < GROUPS);
        // Prefetch next iteration's 8 loads BEFORE reducing current:
        // memory pipe stays busy through the shuffle epilogue.
        if (have_next) load8(nxt, inp, W, next_grp, g, sub);

        const float s = reduce_dot(cur);
        if (sub == 0) {
            const long long row = grp * 4 + g;
            const int m = (int)(row & (M_DIM - 1));
            out[row] = s + __ldg(&bias[m]);
        }

        if (!have_next) break;
        cur = nxt;
        grp = next_grp;
    }
}

extern "C" void kernel_launch(void* const* d_in, const int* in_sizes, int n_in,
                              void* d_out, int out_size)
{
    const float4* inp  = (const float4*)d_in[0];  // inputs  [B, M, I] f32
    const float4* W    = (const float4*)d_in[1];  // Rk_weight [M, I] f32
    const float*  bias = (const float*)d_in[2];   // bias [M] f32
    float*        out  = (float*)d_out;           // [B, M] f32

    // Persistent grid: 152 SMs x 4 blocks (GB300 has 152; works on 148 too).
    const int threads = 256;
    const int blocks  = 152 * 4;

    rowdot_kernel<<<blocks, threads>>>(inp, W, bias, out);
}

// round 12
// speedup vs baseline: 1.8657x; 1.8657x over previous
#include <cuda_runtime.h>
#include <cstdint>

// out[b,m] = dot(inputs[b,m,:], W[m,:]) + bias[m]
// B=1024, M=2048, I=128 (32 float4 per row).
//
// Layout: 8 lanes per output row, 4 output rows per warp.
//   lane = 8*g + sub  (g = output slot 0..3, sub = 0..7)
//   Each lane loads 4 float4 of x and 4 float4 of w  -> MLP=8 per thread.
//   Reduction: 3 butterfly shuffles (xor 4,2,1) reduce all 4 outputs at once.
//
// FINAL (11-round session): runs at the HBM streaming ceiling — ~7.03 TB/s
// effective in the timed loop, 86-87% DRAM-active in ncu. The 1.074 GB
// single-touch input stream is irreducible traffic. Verified invariant to:
// cache-policy hints (R3/4), per-thread MLP 8 vs 16 (R5), occupancy 31-65%
// (R5-R9), store vectorization (R7), 256-bit loads (R9). Persistent
// grid-stride pipelining REGRESSED 1.9x (R11): the one-shot massive grid's
// launch-wide load flood is what sustains bandwidth — keep it.
// Best measured: 153.9 us (1.40x vs the naive warp-per-row baseline).

static constexpr int M_DIM = 2048;
static constexpr long long TOTAL = 1024LL * 2048LL;  // B*M outputs

__global__ __launch_bounds__(256, 6)
void rowdot_kernel(const float4* __restrict__ inp,   // [B*M, 32] float4
                   const float4* __restrict__ W,     // [M, 32] float4
                   const float*  __restrict__ bias,  // [M]
                   float* __restrict__ out)          // [B*M]
{
    const int lane = threadIdx.x & 31;
    const int warp_in_block = threadIdx.x >> 5;
    const long long warp = (long long)blockIdx.x * (blockDim.x >> 5) + warp_in_block;

    const int g   = lane >> 3;   // which of 4 outputs this lane works on
    const int sub = lane & 7;    // position within 8-lane group

    const long long row = warp * 4 + g;     // output index (b*M + m)
    if (row >= TOTAL) return;
    const int m = (int)(row & (M_DIM - 1));

    const float4* __restrict__ xr = inp + row * 32 + sub;
    const float4* __restrict__ wr = W   + (long long)m * 32 + sub;

    // Front-batch all 8 loads (independent) -> MLP=8.
    float4 x0 = xr[0];
    float4 x1 = xr[8];
    float4 x2 = xr[16];
    float4 x3 = xr[24];
    float4 w0 = wr[0];
    float4 w1 = wr[8];
    float4 w2 = wr[16];
    float4 w3 = wr[24];

    float s = x0.x * w0.x + x0.y * w0.y + x0.z * w0.z + x0.w * w0.w;
    s = fmaf(x1.x, w1.x, s); s = fmaf(x1.y, w1.y, s);
    s = fmaf(x1.z, w1.z, s); s = fmaf(x1.w, w1.w, s);
    s = fmaf(x2.x, w2.x, s); s = fmaf(x2.y, w2.y, s);
    s = fmaf(x2.z, w2.z, s); s = fmaf(x2.w, w2.w, s);
    s = fmaf(x3.x, w3.x, s); s = fmaf(x3.y, w3.y, s);
    s = fmaf(x3.z, w3.z, s); s = fmaf(x3.w, w3.w, s);

    // Butterfly within each 8-lane group: reduces all 4 outputs in 3 steps.
    s += __shfl_xor_sync(0xFFFFFFFFu, s, 4);
    s += __shfl_xor_sync(0xFFFFFFFFu, s, 2);
    s += __shfl_xor_sync(0xFFFFFFFFu, s, 1);

    if (sub == 0) {
        out[row] = s + __ldg(&bias[m]);
    }
}

extern "C" void kernel_launch(void* const* d_in, const int* in_sizes, int n_in,
                              void* d_out, int out_size)
{
    const float4* inp  = (const float4*)d_in[0];  // inputs  [B, M, I] f32
    const float4* W    = (const float4*)d_in[1];  // Rk_weight [M, I] f32
    const float*  bias = (const float*)d_in[2];   // bias [M] f32
    float*        out  = (float*)d_out;           // [B, M] f32

    // 4 outputs per warp, 8 warps per block -> 32 outputs per block.
    const int threads = 256;
    const long long outputs_per_block = 32;
    const int blocks = (int)((TOTAL + outputs_per_block - 1) / outputs_per_block);

    rowdot_kernel<<<blocks, threads>>>(inp, W, bias, out);
}